// round 9
// baseline (speedup 1.0000x reference)
#include <cuda_runtime.h>

#define NN     100000
#define NE     1600000
#define IN_CH  32
#define HID    128
#define OUT_CH 32

// Scratch (device globals — no allocation allowed). 16B-aligned for float4 access.
__device__ __align__(16) float g_deg[NN];
__device__ __align__(16) float g_agg1[NN * IN_CH];                 // 12.8 MB
__device__ __align__(16) float g_h[(size_t)NN * HID];              // 51.2 MB
__device__ __align__(16) float g_agg2[(size_t)NN * HID];           // 51.2 MB
__device__ int g_is64;

// Edge-index fetch robust to int32-vs-int64 storage of edge_index.
__device__ __forceinline__ int load_idx(const void* ei, long long pos, int is64) {
    if (is64) return (int)((const long long*)ei)[pos];
    return ((const int*)ei)[pos];
}

// ---------------------------------------------------------------------------
// Detect edge_index dtype. Int64 node ids (< 2^31) -> every odd int32 word is
// the zero high-half. Int32 uniform [0,100000) -> odd words ~never all zero.
// ---------------------------------------------------------------------------
__global__ void k_detect(const int* __restrict__ ei32) {
    if (threadIdx.x == 0 && blockIdx.x == 0) {
        int odd_nonzero = 0;
        for (int i = 1; i < 1024; i += 2) odd_nonzero |= (ei32[i] != 0);
        g_is64 = odd_nonzero ? 0 : 1;
    }
}

// ---------------------------------------------------------------------------
// Zero the accumulators
// ---------------------------------------------------------------------------
__global__ void k_zero() {
    int i = blockIdx.x * blockDim.x + threadIdx.x;
    float4 z = make_float4(0.f, 0.f, 0.f, 0.f);
    if (i < NN * IN_CH / 4) ((float4*)g_agg1)[i] = z;
    if (i < NN * HID / 4)  ((float4*)g_agg2)[i] = z;
    if (i < NN / 4)        ((float4*)g_deg)[i]  = z;
}

// ---------------------------------------------------------------------------
// Layer-1 scatter: agg1[dst] += x[src]  (32 ch), deg[dst] += 1
// 8 threads per edge, each handles one float4 chunk (4 scalar REDs).
// ---------------------------------------------------------------------------
__global__ void k_scatter1(const float* __restrict__ x,
                           const void* __restrict__ ei) {
    long long idx = (long long)blockIdx.x * blockDim.x + threadIdx.x;
    if (idx >= (long long)NE * 8) return;
    int e = (int)(idx >> 3);
    int q = (int)(idx & 7);
    int is64 = g_is64;
    int src = load_idx(ei, e, is64);
    int dst = load_idx(ei, (long long)NE + e, is64);
    if ((unsigned)src >= NN || (unsigned)dst >= NN) return;  // safety net
    float4 v = __ldg(&((const float4*)x)[src * 8 + q]);
    float* a = &g_agg1[dst * IN_CH + q * 4];
    atomicAdd(a + 0, v.x);
    atomicAdd(a + 1, v.y);
    atomicAdd(a + 2, v.z);
    atomicAdd(a + 3, v.w);
    if (q == 0) atomicAdd(&g_deg[dst], 1.0f);
}

// ---------------------------------------------------------------------------
// Layer-1 combine: h = relu((agg1/deg) @ W1l^T + x @ W1r^T + b1)
// 1 warp per 2 nodes, weights transposed in SMEM (sW[c*128 + o]), float4 LDS.
// ---------------------------------------------------------------------------
__global__ __launch_bounds__(128) void k_combine1(
        const float* __restrict__ x,
        const float* __restrict__ W1l,
        const float* __restrict__ W1r,
        const float* __restrict__ b1) {
    __shared__ float4 sWl[IN_CH * HID / 4];   // [c][o/4] -> index c*32 + o4
    __shared__ float4 sWr[IN_CH * HID / 4];
    __shared__ __align__(16) float sb[HID];

    int tid = threadIdx.x;
    float* fWl = (float*)sWl;
    float* fWr = (float*)sWr;
    for (int i = tid; i < IN_CH * HID; i += 128) {
        int c = i >> 7, o = i & 127;          // i = c*128 + o
        fWl[i] = W1l[o * IN_CH + c];
        fWr[i] = W1r[o * IN_CH + c];
    }
    if (tid < HID) sb[tid] = b1[tid];
    __syncthreads();

    int warp = tid >> 5, lane = tid & 31;
    int n0 = blockIdx.x * 8 + warp * 2;
    if (n0 >= NN) return;
    int n1 = n0 + 1;

    float invd0 = 1.0f / fmaxf(g_deg[n0], 1.0f);
    float invd1 = 1.0f / fmaxf(g_deg[n1], 1.0f);

    const float4* a0p = (const float4*)&g_agg1[n0 * IN_CH];
    const float4* a1p = (const float4*)&g_agg1[n1 * IN_CH];
    const float4* x0p = (const float4*)&x[n0 * IN_CH];
    const float4* x1p = (const float4*)&x[n1 * IN_CH];

    float4 acc0 = make_float4(0.f, 0.f, 0.f, 0.f);
    float4 acc1 = make_float4(0.f, 0.f, 0.f, 0.f);

#pragma unroll
    for (int c4 = 0; c4 < IN_CH / 4; c4++) {
        float4 a0 = a0p[c4], a1 = a1p[c4];
        float4 x0 = x0p[c4], x1 = x1p[c4];
#pragma unroll
        for (int j = 0; j < 4; j++) {
            int c = c4 * 4 + j;
            float av0 = ((float*)&a0)[j] * invd0;
            float av1 = ((float*)&a1)[j] * invd1;
            float xv0 = ((float*)&x0)[j];
            float xv1 = ((float*)&x1)[j];
            float4 wl = sWl[c * 32 + lane];
            float4 wr = sWr[c * 32 + lane];
            acc0.x = fmaf(av0, wl.x, fmaf(xv0, wr.x, acc0.x));
            acc0.y = fmaf(av0, wl.y, fmaf(xv0, wr.y, acc0.y));
            acc0.z = fmaf(av0, wl.z, fmaf(xv0, wr.z, acc0.z));
            acc0.w = fmaf(av0, wl.w, fmaf(xv0, wr.w, acc0.w));
            acc1.x = fmaf(av1, wl.x, fmaf(xv1, wr.x, acc1.x));
            acc1.y = fmaf(av1, wl.y, fmaf(xv1, wr.y, acc1.y));
            acc1.z = fmaf(av1, wl.z, fmaf(xv1, wr.z, acc1.z));
            acc1.w = fmaf(av1, wl.w, fmaf(xv1, wr.w, acc1.w));
        }
    }
    float4 bb = ((float4*)sb)[lane];
    float4 o0, o1;
    o0.x = fmaxf(acc0.x + bb.x, 0.f); o0.y = fmaxf(acc0.y + bb.y, 0.f);
    o0.z = fmaxf(acc0.z + bb.z, 0.f); o0.w = fmaxf(acc0.w + bb.w, 0.f);
    o1.x = fmaxf(acc1.x + bb.x, 0.f); o1.y = fmaxf(acc1.y + bb.y, 0.f);
    o1.z = fmaxf(acc1.z + bb.z, 0.f); o1.w = fmaxf(acc1.w + bb.w, 0.f);
    ((float4*)g_h)[n0 * (HID / 4) + lane] = o0;
    ((float4*)g_h)[n1 * (HID / 4) + lane] = o1;
}

// ---------------------------------------------------------------------------
// Layer-2 scatter: agg2[dst] += h[src]  (128 ch). One warp per edge,
// each lane moves one float4 (4 scalar REDs).
// ---------------------------------------------------------------------------
__global__ void k_scatter2(const void* __restrict__ ei) {
    long long t = (long long)blockIdx.x * blockDim.x + threadIdx.x;
    int w = (int)(t >> 5);
    int lane = threadIdx.x & 31;
    if (w >= NE) return;
    int is64 = g_is64;
    int src = load_idx(ei, w, is64);
    int dst = load_idx(ei, (long long)NE + w, is64);
    if ((unsigned)src >= NN || (unsigned)dst >= NN) return;  // safety net
    float4 v = ((const float4*)g_h)[(size_t)src * (HID / 4) + lane];
    float* a = &g_agg2[(size_t)dst * HID + lane * 4];
    atomicAdd(a + 0, v.x);
    atomicAdd(a + 1, v.y);
    atomicAdd(a + 2, v.z);
    atomicAdd(a + 3, v.w);
}

// ---------------------------------------------------------------------------
// Layer-2 combine: out = (agg2/deg) @ W2l^T + h @ W2r^T + b2
// 128 threads/block, thread = (node-slot, output-quad g in 0..7), 2 nodes/thread.
// ---------------------------------------------------------------------------
__global__ __launch_bounds__(128) void k_combine2(
        const float* __restrict__ W2l,
        const float* __restrict__ W2r,
        const float* __restrict__ b2,
        float* __restrict__ out) {
    __shared__ float4 sWl[HID * OUT_CH / 4];  // [c][o/4] -> index c*8 + g
    __shared__ float4 sWr[HID * OUT_CH / 4];
    __shared__ __align__(16) float sb[OUT_CH];

    int tid = threadIdx.x;
    float* fWl = (float*)sWl;
    float* fWr = (float*)sWr;
    for (int i = tid; i < HID * OUT_CH; i += 128) {
        int c = i >> 5, o = i & 31;           // i = c*32 + o
        fWl[i] = W2l[o * HID + c];
        fWr[i] = W2r[o * HID + c];
    }
    if (tid < OUT_CH) sb[tid] = b2[tid];
    __syncthreads();

    int g  = tid & 7;     // output quad (4 of 32 output channels)
    int ln = tid >> 3;    // 0..15
    int n0 = blockIdx.x * 32 + ln;
    if (n0 >= NN) return;
    int n1 = n0 + 16;

    float invd0 = 1.0f / fmaxf(g_deg[n0], 1.0f);
    float invd1 = 1.0f / fmaxf(g_deg[n1], 1.0f);

    const float4* a0p = (const float4*)&g_agg2[(size_t)n0 * HID];
    const float4* a1p = (const float4*)&g_agg2[(size_t)n1 * HID];
    const float4* h0p = (const float4*)&g_h[(size_t)n0 * HID];
    const float4* h1p = (const float4*)&g_h[(size_t)n1 * HID];

    float4 acc0 = make_float4(0.f, 0.f, 0.f, 0.f);
    float4 acc1 = make_float4(0.f, 0.f, 0.f, 0.f);

#pragma unroll 4
    for (int c4 = 0; c4 < HID / 4; c4++) {
        float4 a0 = a0p[c4], a1 = a1p[c4];
        float4 h0 = h0p[c4], h1 = h1p[c4];
#pragma unroll
        for (int j = 0; j < 4; j++) {
            int c = c4 * 4 + j;
            float av0 = ((float*)&a0)[j] * invd0;
            float av1 = ((float*)&a1)[j] * invd1;
            float hv0 = ((float*)&h0)[j];
            float hv1 = ((float*)&h1)[j];
            float4 wl = sWl[c * 8 + g];
            float4 wr = sWr[c * 8 + g];
            acc0.x = fmaf(av0, wl.x, fmaf(hv0, wr.x, acc0.x));
            acc0.y = fmaf(av0, wl.y, fmaf(hv0, wr.y, acc0.y));
            acc0.z = fmaf(av0, wl.z, fmaf(hv0, wr.z, acc0.z));
            acc0.w = fmaf(av0, wl.w, fmaf(hv0, wr.w, acc0.w));
            acc1.x = fmaf(av1, wl.x, fmaf(hv1, wr.x, acc1.x));
            acc1.y = fmaf(av1, wl.y, fmaf(hv1, wr.y, acc1.y));
            acc1.z = fmaf(av1, wl.z, fmaf(hv1, wr.z, acc1.z));
            acc1.w = fmaf(av1, wl.w, fmaf(hv1, wr.w, acc1.w));
        }
    }
    float4 bb = ((float4*)sb)[g];
    float4 o0, o1;
    o0.x = acc0.x + bb.x; o0.y = acc0.y + bb.y;
    o0.z = acc0.z + bb.z; o0.w = acc0.w + bb.w;
    o1.x = acc1.x + bb.x; o1.y = acc1.y + bb.y;
    o1.z = acc1.z + bb.z; o1.w = acc1.w + bb.w;
    ((float4*)out)[n0 * (OUT_CH / 4) + g] = o0;
    ((float4*)out)[n1 * (OUT_CH / 4) + g] = o1;
}

// ---------------------------------------------------------------------------
extern "C" void kernel_launch(void* const* d_in, const int* in_sizes, int n_in,
                              void* d_out, int out_size) {
    const float* x   = (const float*)d_in[0];
    const void*  ei  = d_in[1];               // int32 or int64 — detected on device
    const float* W1l = (const float*)d_in[2];
    const float* W1r = (const float*)d_in[3];
    const float* b1  = (const float*)d_in[4];
    const float* W2l = (const float*)d_in[5];
    const float* W2r = (const float*)d_in[6];
    const float* b2  = (const float*)d_in[7];
    float* out = (float*)d_out;

    k_detect<<<1, 32>>>((const int*)ei);
    k_zero<<<(NN * HID / 4 + 255) / 256, 256>>>();
    k_scatter1<<<(int)(((long long)NE * 8 + 255) / 256), 256>>>(x, ei);
    k_combine1<<<(NN + 7) / 8, 128>>>(x, W1l, W1r, b1);
    k_scatter2<<<(int)(((long long)NE * 32 + 255) / 256), 256>>>(ei);
    k_combine2<<<(NN + 31) / 32, 128>>>(W2l, W2r, b2, out);
}

// round 10
// speedup vs baseline: 2.2986x; 2.2986x over previous
#include <cuda_runtime.h>

#define NN     100000
#define NE     1600000
#define IN_CH  32
#define HID    128
#define OUT_CH 32

// ---------------- Scratch (device globals; no allocation allowed) ----------
__device__ int   g_is64;
__device__ int   g_cnt[NN];                 // degree histogram (int)
__device__ int   g_fill[NN];                // CSR fill cursors
__device__ int   g_rowptr[NN + 1];
__device__ int   g_col[NE];                 // CSR neighbor (src) list, 6.4 MB
__device__ __align__(16) float g_invdeg[NN];
__device__ __align__(16) float g_agg1[NN * IN_CH];        // mean-aggregated x
__device__ __align__(16) float g_h[(size_t)NN * HID];     // layer-1 output
__device__ __align__(16) float g_agg2[(size_t)NN * HID];  // mean-aggregated h

// Edge-index fetch robust to int32-vs-int64 storage of edge_index.
__device__ __forceinline__ int load_idx(const void* ei, long long pos, int is64) {
    if (is64) return (int)((const long long*)ei)[pos];
    return ((const int*)ei)[pos];
}

__global__ void k_detect(const int* __restrict__ ei32) {
    if (threadIdx.x == 0 && blockIdx.x == 0) {
        int odd_nonzero = 0;
        for (int i = 1; i < 1024; i += 2) odd_nonzero |= (ei32[i] != 0);
        g_is64 = odd_nonzero ? 0 : 1;
    }
}

// ---------------- CSR build ------------------------------------------------
__global__ void k_zero_cnt() {
    int i = blockIdx.x * blockDim.x + threadIdx.x;
    if (i < NN) { g_cnt[i] = 0; g_fill[i] = 0; }
}

__global__ void k_hist(const void* __restrict__ ei) {
    int e = blockIdx.x * blockDim.x + threadIdx.x;
    if (e >= NE) return;
    int dst = load_idx(ei, (long long)NE + e, g_is64);
    if ((unsigned)dst < NN) atomicAdd(&g_cnt[dst], 1);
}

// Single-block exclusive scan over g_cnt -> g_rowptr, plus invdeg.
__global__ __launch_bounds__(1024) void k_scan() {
    __shared__ int part[1024];
    int tid = threadIdx.x;
    const int PER = (NN + 1023) / 1024;     // 98
    int base = tid * PER;
    int s = 0;
    for (int i = 0; i < PER; i++) {
        int idx = base + i;
        if (idx < NN) s += g_cnt[idx];
    }
    part[tid] = s;
    __syncthreads();
    for (int off = 1; off < 1024; off <<= 1) {
        int v = 0;
        if (tid >= off) v = part[tid - off];
        __syncthreads();
        if (tid >= off) part[tid] += v;
        __syncthreads();
    }
    int run = (tid == 0) ? 0 : part[tid - 1];
    for (int i = 0; i < PER; i++) {
        int idx = base + i;
        if (idx < NN) {
            g_rowptr[idx] = run;
            int c = g_cnt[idx];
            run += c;
            g_invdeg[idx] = 1.0f / fmaxf((float)c, 1.0f);
        }
    }
    if (tid == 1023) g_rowptr[NN] = run;
}

__global__ void k_fill(const void* __restrict__ ei) {
    int e = blockIdx.x * blockDim.x + threadIdx.x;
    if (e >= NE) return;
    int is64 = g_is64;
    int src = load_idx(ei, e, is64);
    int dst = load_idx(ei, (long long)NE + e, is64);
    if ((unsigned)src >= NN || (unsigned)dst >= NN) return;
    int pos = g_rowptr[dst] + atomicAdd(&g_fill[dst], 1);
    g_col[pos] = src;
}

// ---------------- Layer-1 gather: agg1[n] = mean_{s in N(n)} x[s]  ---------
// One warp per node; lane = channel. Coalesced 128B per neighbor, no atomics.
__global__ __launch_bounds__(256) void k_gather1(const float* __restrict__ x) {
    int w = (blockIdx.x * blockDim.x + threadIdx.x) >> 5;
    int lane = threadIdx.x & 31;
    if (w >= NN) return;
    int beg = g_rowptr[w], end = g_rowptr[w + 1];
    float acc0 = 0.f, acc1 = 0.f;
    int i = beg;
    for (; i + 1 < end; i += 2) {
        int s0 = g_col[i], s1 = g_col[i + 1];
        acc0 += __ldg(&x[s0 * IN_CH + lane]);
        acc1 += __ldg(&x[s1 * IN_CH + lane]);
    }
    if (i < end) acc0 += __ldg(&x[g_col[i] * IN_CH + lane]);
    g_agg1[w * IN_CH + lane] = (acc0 + acc1) * g_invdeg[w];
}

// ---------------- Layer-1 combine: h = relu(agg1@W1l^T + x@W1r^T + b1) -----
// 256 threads, 256 nodes/block. Coalesced weight load + SMEM transpose.
// Warp processes 4 nodes per pass; lane = output float4 (128 outs / 32 lanes).
__global__ __launch_bounds__(256) void k_combine1(
        const float* __restrict__ x,
        const float* __restrict__ W1l,
        const float* __restrict__ W1r,
        const float* __restrict__ b1) {
    __shared__ __align__(16) float sWl[IN_CH * HID];   // [c*128 + o]
    __shared__ __align__(16) float sWr[IN_CH * HID];
    __shared__ __align__(16) float sb[HID];

    int tid = threadIdx.x;
    const float4* Wl4 = (const float4*)W1l;            // elem i*4 = o*32 + c4*4
    const float4* Wr4 = (const float4*)W1r;
    for (int i = tid; i < IN_CH * HID / 4; i += 256) {
        int o = i >> 3, c4 = i & 7;
        float4 v = Wl4[i];
        sWl[(c4 * 4 + 0) * HID + o] = v.x;
        sWl[(c4 * 4 + 1) * HID + o] = v.y;
        sWl[(c4 * 4 + 2) * HID + o] = v.z;
        sWl[(c4 * 4 + 3) * HID + o] = v.w;
        v = Wr4[i];
        sWr[(c4 * 4 + 0) * HID + o] = v.x;
        sWr[(c4 * 4 + 1) * HID + o] = v.y;
        sWr[(c4 * 4 + 2) * HID + o] = v.z;
        sWr[(c4 * 4 + 3) * HID + o] = v.w;
    }
    if (tid < HID) sb[tid] = b1[tid];
    __syncthreads();

    int warp = tid >> 5, lane = tid & 31;
    int nbase = blockIdx.x * 256;
    const float4* a4 = (const float4*)g_agg1;
    const float4* x4 = (const float4*)x;
    const float4* sWl4 = (const float4*)sWl;
    const float4* sWr4 = (const float4*)sWr;
    float4 bb = ((const float4*)sb)[lane];
    float4 z = make_float4(0.f, 0.f, 0.f, 0.f);

    for (int it = warp; it < 64; it += 8) {
        int n0 = nbase + it * 4;
        if (n0 >= NN) break;
        float4 acc[4] = {z, z, z, z};
#pragma unroll
        for (int c4 = 0; c4 < 8; c4++) {
            float4 av[4], xv[4];
#pragma unroll
            for (int k = 0; k < 4; k++) {
                int n = n0 + k;
                bool ok = (n < NN);
                av[k] = ok ? a4[n * 8 + c4] : z;
                xv[k] = ok ? x4[n * 8 + c4] : z;
            }
#pragma unroll
            for (int j = 0; j < 4; j++) {
                int c = c4 * 4 + j;
                float4 wl = sWl4[c * 32 + lane];
                float4 wr = sWr4[c * 32 + lane];
#pragma unroll
                for (int k = 0; k < 4; k++) {
                    float a = ((const float*)&av[k])[j];
                    float xx = ((const float*)&xv[k])[j];
                    acc[k].x = fmaf(a, wl.x, fmaf(xx, wr.x, acc[k].x));
                    acc[k].y = fmaf(a, wl.y, fmaf(xx, wr.y, acc[k].y));
                    acc[k].z = fmaf(a, wl.z, fmaf(xx, wr.z, acc[k].z));
                    acc[k].w = fmaf(a, wl.w, fmaf(xx, wr.w, acc[k].w));
                }
            }
        }
#pragma unroll
        for (int k = 0; k < 4; k++) {
            int n = n0 + k;
            if (n < NN) {
                float4 o;
                o.x = fmaxf(acc[k].x + bb.x, 0.f);
                o.y = fmaxf(acc[k].y + bb.y, 0.f);
                o.z = fmaxf(acc[k].z + bb.z, 0.f);
                o.w = fmaxf(acc[k].w + bb.w, 0.f);
                ((float4*)g_h)[(size_t)n * (HID / 4) + lane] = o;
            }
        }
    }
}

// ---------------- Layer-2 gather: agg2[n] = mean_{s in N(n)} h[s] ----------
// One warp per node; lane = float4 channel group (128 ch / 32 lanes).
__global__ __launch_bounds__(256) void k_gather2() {
    int w = (blockIdx.x * blockDim.x + threadIdx.x) >> 5;
    int lane = threadIdx.x & 31;
    if (w >= NN) return;
    int beg = g_rowptr[w], end = g_rowptr[w + 1];
    const float4* h4 = (const float4*)g_h;
    float4 a0 = make_float4(0.f, 0.f, 0.f, 0.f);
    float4 a1 = make_float4(0.f, 0.f, 0.f, 0.f);
    int i = beg;
    for (; i + 1 < end; i += 2) {
        int s0 = g_col[i], s1 = g_col[i + 1];
        float4 v0 = h4[(size_t)s0 * 32 + lane];
        float4 v1 = h4[(size_t)s1 * 32 + lane];
        a0.x += v0.x; a0.y += v0.y; a0.z += v0.z; a0.w += v0.w;
        a1.x += v1.x; a1.y += v1.y; a1.z += v1.z; a1.w += v1.w;
    }
    if (i < end) {
        float4 v0 = h4[(size_t)g_col[i] * 32 + lane];
        a0.x += v0.x; a0.y += v0.y; a0.z += v0.z; a0.w += v0.w;
    }
    float inv = g_invdeg[w];
    float4 o;
    o.x = (a0.x + a1.x) * inv; o.y = (a0.y + a1.y) * inv;
    o.z = (a0.z + a1.z) * inv; o.w = (a0.w + a1.w) * inv;
    ((float4*)g_agg2)[(size_t)w * 32 + lane] = o;
}

// ---------------- Layer-2 combine: out = agg2@W2l^T + h@W2r^T + b2 ---------
// 256 threads, 256 nodes/block. lane = (node_sub, out-quad): 4 nodes/warp/pass.
__global__ __launch_bounds__(256) void k_combine2(
        const float* __restrict__ W2l,
        const float* __restrict__ W2r,
        const float* __restrict__ b2,
        float* __restrict__ out) {
    __shared__ __align__(16) float sWl[HID * OUT_CH];  // [c*32 + o]
    __shared__ __align__(16) float sWr[HID * OUT_CH];
    __shared__ __align__(16) float sb[OUT_CH];

    int tid = threadIdx.x;
    const float4* Wl4 = (const float4*)W2l;            // elem i*4 = o*128 + c4*4
    const float4* Wr4 = (const float4*)W2r;
    for (int i = tid; i < HID * OUT_CH / 4; i += 256) {
        int o = i >> 5, c4 = i & 31;
        float4 v = Wl4[i];
        sWl[(c4 * 4 + 0) * OUT_CH + o] = v.x;
        sWl[(c4 * 4 + 1) * OUT_CH + o] = v.y;
        sWl[(c4 * 4 + 2) * OUT_CH + o] = v.z;
        sWl[(c4 * 4 + 3) * OUT_CH + o] = v.w;
        v = Wr4[i];
        sWr[(c4 * 4 + 0) * OUT_CH + o] = v.x;
        sWr[(c4 * 4 + 1) * OUT_CH + o] = v.y;
        sWr[(c4 * 4 + 2) * OUT_CH + o] = v.z;
        sWr[(c4 * 4 + 3) * OUT_CH + o] = v.w;
    }
    if (tid < OUT_CH) sb[tid] = b2[tid];
    __syncthreads();

    int warp = tid >> 5, lane = tid & 31;
    int ksub = lane >> 3;      // node sub-index 0..3
    int g = lane & 7;          // output quad 0..7
    int nbase = blockIdx.x * 256;
    const float4* a4 = (const float4*)g_agg2;
    const float4* h4 = (const float4*)g_h;
    const float4* sWl4 = (const float4*)sWl;
    const float4* sWr4 = (const float4*)sWr;
    float4 bb = ((const float4*)sb)[g];

    for (int it = warp; it < 64; it += 8) {
        int n = nbase + it * 4 + ksub;
        bool ok = (n < NN);
        size_t nb = ok ? (size_t)n * 32 : 0;
        float4 acc = make_float4(0.f, 0.f, 0.f, 0.f);
#pragma unroll 4
        for (int c4 = 0; c4 < 32; c4++) {
            float4 av = a4[nb + c4];
            float4 hv = h4[nb + c4];
#pragma unroll
            for (int j = 0; j < 4; j++) {
                int c = c4 * 4 + j;
                float a = ((const float*)&av)[j];
                float hh = ((const float*)&hv)[j];
                float4 wl = sWl4[c * 8 + g];
                float4 wr = sWr4[c * 8 + g];
                acc.x = fmaf(a, wl.x, fmaf(hh, wr.x, acc.x));
                acc.y = fmaf(a, wl.y, fmaf(hh, wr.y, acc.y));
                acc.z = fmaf(a, wl.z, fmaf(hh, wr.z, acc.z));
                acc.w = fmaf(a, wl.w, fmaf(hh, wr.w, acc.w));
            }
        }
        if (ok) {
            float4 o;
            o.x = acc.x + bb.x; o.y = acc.y + bb.y;
            o.z = acc.z + bb.z; o.w = acc.w + bb.w;
            ((float4*)out)[(size_t)n * (OUT_CH / 4) + g] = o;
        }
    }
}

// ---------------------------------------------------------------------------
extern "C" void kernel_launch(void* const* d_in, const int* in_sizes, int n_in,
                              void* d_out, int out_size) {
    const float* x   = (const float*)d_in[0];
    const void*  ei  = d_in[1];               // int32 or int64 — detected on device
    const float* W1l = (const float*)d_in[2];
    const float* W1r = (const float*)d_in[3];
    const float* b1  = (const float*)d_in[4];
    const float* W2l = (const float*)d_in[5];
    const float* W2r = (const float*)d_in[6];
    const float* b2  = (const float*)d_in[7];
    float* out = (float*)d_out;

    const int EB = (NE + 255) / 256;          // 6250
    const int NB = (NN + 255) / 256;          // 391

    k_detect<<<1, 32>>>((const int*)ei);
    k_zero_cnt<<<NB, 256>>>();
    k_hist<<<EB, 256>>>(ei);
    k_scan<<<1, 1024>>>();
    k_fill<<<EB, 256>>>(ei);
    k_gather1<<<(NN * 32 + 255) / 256, 256>>>(x);
    k_combine1<<<NB, 256>>>(x, W1l, W1r, b1);
    k_gather2<<<(NN * 32 + 255) / 256, 256>>>();
    k_combine2<<<NB, 256>>>(W2l, W2r, b2, out);
}

// round 11
// speedup vs baseline: 3.8694x; 1.6834x over previous
#include <cuda_runtime.h>

#define NN     100000
#define NE     1600000
#define IN_CH  32
#define HID    128
#define OUT_CH 32
#define NB_N   ((NN + 255) / 256)   // 391 node blocks

// ---------------- Scratch (device globals; no allocation allowed) ----------
__device__ int   g_is64;
__device__ int   g_cnt[NN];
__device__ int   g_fill[NN];
__device__ int   g_rowptr[NN + 1];
__device__ int   g_col[NE];
__device__ int   g_bsum[NB_N];
__device__ int   g_boff[NB_N];
__device__ __align__(16) float g_invdeg[NN];
__device__ __align__(16) float g_agg1[NN * IN_CH];        // mean-aggregated x
__device__ __align__(16) float g_h[(size_t)NN * HID];     // layer-1 output
__device__ __align__(16) float g_zl[NN * OUT_CH];         // h @ W2l^T
__device__ __align__(16) float g_r2[NN * OUT_CH];         // h @ W2r^T

__device__ __forceinline__ int load_idx(const void* ei, long long pos, int is64) {
    if (is64) return (int)((const long long*)ei)[pos];
    return ((const int*)ei)[pos];
}

__global__ void k_detect(const int* __restrict__ ei32) {
    if (threadIdx.x == 0 && blockIdx.x == 0) {
        int odd_nonzero = 0;
        for (int i = 1; i < 1024; i += 2) odd_nonzero |= (ei32[i] != 0);
        g_is64 = odd_nonzero ? 0 : 1;
    }
}

// ---------------- CSR build ------------------------------------------------
__global__ void k_zero_cnt() {
    int i = blockIdx.x * blockDim.x + threadIdx.x;
    if (i < NN) { g_cnt[i] = 0; g_fill[i] = 0; }
}

__global__ void k_hist(const void* __restrict__ ei) {
    int e = blockIdx.x * blockDim.x + threadIdx.x;
    if (e >= NE) return;
    int dst = load_idx(ei, (long long)NE + e, g_is64);
    if ((unsigned)dst < NN) atomicAdd(&g_cnt[dst], 1);
}

// Phase A: per-block (256 counts) reduction -> g_bsum
__global__ __launch_bounds__(256) void k_scanA() {
    __shared__ int s[256];
    int tid = threadIdx.x;
    int idx = blockIdx.x * 256 + tid;
    s[tid] = (idx < NN) ? g_cnt[idx] : 0;
    __syncthreads();
    for (int off = 128; off > 0; off >>= 1) {
        if (tid < off) s[tid] += s[tid + off];
        __syncthreads();
    }
    if (tid == 0) g_bsum[blockIdx.x] = s[0];
}

// Phase B: scan the 391 block sums (one tiny block)
__global__ __launch_bounds__(512) void k_scanB() {
    __shared__ int s[512];
    int tid = threadIdx.x;
    int v = (tid < NB_N) ? g_bsum[tid] : 0;
    s[tid] = v;
    __syncthreads();
    for (int off = 1; off < 512; off <<= 1) {
        int t = 0;
        if (tid >= off) t = s[tid - off];
        __syncthreads();
        if (tid >= off) s[tid] += t;
        __syncthreads();
    }
    if (tid < NB_N) g_boff[tid] = s[tid] - v;          // exclusive
    if (tid == NB_N - 1) g_rowptr[NN] = s[tid];        // total
}

// Phase C: per-block exclusive scan + global offset -> rowptr, invdeg
__global__ __launch_bounds__(256) void k_scanC() {
    __shared__ int s[256];
    int tid = threadIdx.x;
    int idx = blockIdx.x * 256 + tid;
    int c = (idx < NN) ? g_cnt[idx] : 0;
    s[tid] = c;
    __syncthreads();
    for (int off = 1; off < 256; off <<= 1) {
        int t = 0;
        if (tid >= off) t = s[tid - off];
        __syncthreads();
        if (tid >= off) s[tid] += t;
        __syncthreads();
    }
    if (idx < NN) {
        g_rowptr[idx] = g_boff[blockIdx.x] + s[tid] - c;
        g_invdeg[idx] = 1.0f / fmaxf((float)c, 1.0f);
    }
}

__global__ void k_fill(const void* __restrict__ ei) {
    int e = blockIdx.x * blockDim.x + threadIdx.x;
    if (e >= NE) return;
    int is64 = g_is64;
    int src = load_idx(ei, e, is64);
    int dst = load_idx(ei, (long long)NE + e, is64);
    if ((unsigned)src >= NN || (unsigned)dst >= NN) return;
    int pos = g_rowptr[dst] + atomicAdd(&g_fill[dst], 1);
    g_col[pos] = src;
}

// ---------------- Layer-1 gather: agg1[n] = mean_{s in N(n)} x[s]  ---------
__global__ __launch_bounds__(256) void k_gather1(const float* __restrict__ x) {
    int w = (blockIdx.x * blockDim.x + threadIdx.x) >> 5;
    int lane = threadIdx.x & 31;
    if (w >= NN) return;
    int beg = g_rowptr[w], end = g_rowptr[w + 1];
    float acc0 = 0.f, acc1 = 0.f;
    int i = beg;
    for (; i + 1 < end; i += 2) {
        int s0 = g_col[i], s1 = g_col[i + 1];
        acc0 += __ldg(&x[s0 * IN_CH + lane]);
        acc1 += __ldg(&x[s1 * IN_CH + lane]);
    }
    if (i < end) acc0 += __ldg(&x[g_col[i] * IN_CH + lane]);
    g_agg1[w * IN_CH + lane] = (acc0 + acc1) * g_invdeg[w];
}

// ---------------- Layer-1 combine: h = relu(agg1@W1l^T + x@W1r^T + b1) -----
__global__ __launch_bounds__(256) void k_combine1(
        const float* __restrict__ x,
        const float* __restrict__ W1l,
        const float* __restrict__ W1r,
        const float* __restrict__ b1) {
    __shared__ __align__(16) float sWl[IN_CH * HID];   // [c*128 + o]
    __shared__ __align__(16) float sWr[IN_CH * HID];
    __shared__ __align__(16) float sb[HID];

    int tid = threadIdx.x;
    const float4* Wl4 = (const float4*)W1l;            // elem i*4 = o*32 + c4*4
    const float4* Wr4 = (const float4*)W1r;
    for (int i = tid; i < IN_CH * HID / 4; i += 256) {
        int o = i >> 3, c4 = i & 7;
        float4 v = Wl4[i];
        sWl[(c4 * 4 + 0) * HID + o] = v.x;
        sWl[(c4 * 4 + 1) * HID + o] = v.y;
        sWl[(c4 * 4 + 2) * HID + o] = v.z;
        sWl[(c4 * 4 + 3) * HID + o] = v.w;
        v = Wr4[i];
        sWr[(c4 * 4 + 0) * HID + o] = v.x;
        sWr[(c4 * 4 + 1) * HID + o] = v.y;
        sWr[(c4 * 4 + 2) * HID + o] = v.z;
        sWr[(c4 * 4 + 3) * HID + o] = v.w;
    }
    if (tid < HID) sb[tid] = b1[tid];
    __syncthreads();

    int warp = tid >> 5, lane = tid & 31;
    int nbase = blockIdx.x * 256;
    const float4* a4 = (const float4*)g_agg1;
    const float4* x4 = (const float4*)x;
    const float4* sWl4 = (const float4*)sWl;
    const float4* sWr4 = (const float4*)sWr;
    float4 bb = ((const float4*)sb)[lane];
    float4 z = make_float4(0.f, 0.f, 0.f, 0.f);

    for (int it = warp; it < 64; it += 8) {
        int n0 = nbase + it * 4;
        if (n0 >= NN) break;
        float4 acc[4] = {z, z, z, z};
#pragma unroll
        for (int c4 = 0; c4 < 8; c4++) {
            float4 av[4], xv[4];
#pragma unroll
            for (int k = 0; k < 4; k++) {
                int n = n0 + k;
                bool ok = (n < NN);
                av[k] = ok ? a4[n * 8 + c4] : z;
                xv[k] = ok ? x4[n * 8 + c4] : z;
            }
#pragma unroll
            for (int j = 0; j < 4; j++) {
                int c = c4 * 4 + j;
                float4 wl = sWl4[c * 32 + lane];
                float4 wr = sWr4[c * 32 + lane];
#pragma unroll
                for (int k = 0; k < 4; k++) {
                    float a = ((const float*)&av[k])[j];
                    float xx = ((const float*)&xv[k])[j];
                    acc[k].x = fmaf(a, wl.x, fmaf(xx, wr.x, acc[k].x));
                    acc[k].y = fmaf(a, wl.y, fmaf(xx, wr.y, acc[k].y));
                    acc[k].z = fmaf(a, wl.z, fmaf(xx, wr.z, acc[k].z));
                    acc[k].w = fmaf(a, wl.w, fmaf(xx, wr.w, acc[k].w));
                }
            }
        }
#pragma unroll
        for (int k = 0; k < 4; k++) {
            int n = n0 + k;
            if (n < NN) {
                float4 o;
                o.x = fmaxf(acc[k].x + bb.x, 0.f);
                o.y = fmaxf(acc[k].y + bb.y, 0.f);
                o.z = fmaxf(acc[k].z + bb.z, 0.f);
                o.w = fmaxf(acc[k].w + bb.w, 0.f);
                ((float4*)g_h)[(size_t)n * (HID / 4) + lane] = o;
            }
        }
    }
}

// ---------------- Layer-2 dense pre-pass: zl = h@W2l^T, r2 = h@W2r^T -------
// (aggregation is linear: mean(h) @ W = mean(h @ W), so project BEFORE gather)
__global__ __launch_bounds__(256) void k_pre2(
        const float* __restrict__ W2l,
        const float* __restrict__ W2r) {
    __shared__ __align__(16) float sWl[HID * OUT_CH];  // [c*32 + o]
    __shared__ __align__(16) float sWr[HID * OUT_CH];

    int tid = threadIdx.x;
    const float4* Wl4 = (const float4*)W2l;            // elem i*4 = o*128 + c4*4
    const float4* Wr4 = (const float4*)W2r;
    for (int i = tid; i < HID * OUT_CH / 4; i += 256) {
        int o = i >> 5, c4 = i & 31;
        float4 v = Wl4[i];
        sWl[(c4 * 4 + 0) * OUT_CH + o] = v.x;
        sWl[(c4 * 4 + 1) * OUT_CH + o] = v.y;
        sWl[(c4 * 4 + 2) * OUT_CH + o] = v.z;
        sWl[(c4 * 4 + 3) * OUT_CH + o] = v.w;
        v = Wr4[i];
        sWr[(c4 * 4 + 0) * OUT_CH + o] = v.x;
        sWr[(c4 * 4 + 1) * OUT_CH + o] = v.y;
        sWr[(c4 * 4 + 2) * OUT_CH + o] = v.z;
        sWr[(c4 * 4 + 3) * OUT_CH + o] = v.w;
    }
    __syncthreads();

    int warp = tid >> 5, lane = tid & 31;
    int ksub = lane >> 3;      // node sub-index 0..3
    int g = lane & 7;          // output quad 0..7
    int nbase = blockIdx.x * 256;
    const float4* h4 = (const float4*)g_h;
    const float4* sWl4 = (const float4*)sWl;
    const float4* sWr4 = (const float4*)sWr;

    for (int it = warp; it < 64; it += 8) {
        int n = nbase + it * 4 + ksub;
        bool ok = (n < NN);
        size_t nb = ok ? (size_t)n * 32 : 0;
        float4 accl = make_float4(0.f, 0.f, 0.f, 0.f);
        float4 accr = make_float4(0.f, 0.f, 0.f, 0.f);
#pragma unroll 4
        for (int c4 = 0; c4 < 32; c4++) {
            float4 hv = h4[nb + c4];
#pragma unroll
            for (int j = 0; j < 4; j++) {
                int c = c4 * 4 + j;
                float hh = ((const float*)&hv)[j];
                float4 wl = sWl4[c * 8 + g];
                float4 wr = sWr4[c * 8 + g];
                accl.x = fmaf(hh, wl.x, accl.x);
                accl.y = fmaf(hh, wl.y, accl.y);
                accl.z = fmaf(hh, wl.z, accl.z);
                accl.w = fmaf(hh, wl.w, accl.w);
                accr.x = fmaf(hh, wr.x, accr.x);
                accr.y = fmaf(hh, wr.y, accr.y);
                accr.z = fmaf(hh, wr.z, accr.z);
                accr.w = fmaf(hh, wr.w, accr.w);
            }
        }
        if (ok) {
            ((float4*)g_zl)[n * (OUT_CH / 4) + g] = accl;
            ((float4*)g_r2)[n * (OUT_CH / 4) + g] = accr;
        }
    }
}

// ---------------- Output: out[n] = mean_{s in N(n)} zl[s] + r2[n] + b2 -----
__global__ __launch_bounds__(256) void k_out(const float* __restrict__ b2,
                                             float* __restrict__ out) {
    int w = (blockIdx.x * blockDim.x + threadIdx.x) >> 5;
    int lane = threadIdx.x & 31;
    if (w >= NN) return;
    int beg = g_rowptr[w], end = g_rowptr[w + 1];
    float a0 = 0.f, a1 = 0.f, a2 = 0.f, a3 = 0.f;
    int i = beg;
    for (; i + 3 < end; i += 4) {
        int s0 = g_col[i], s1 = g_col[i + 1], s2 = g_col[i + 2], s3 = g_col[i + 3];
        a0 += __ldg(&g_zl[s0 * OUT_CH + lane]);
        a1 += __ldg(&g_zl[s1 * OUT_CH + lane]);
        a2 += __ldg(&g_zl[s2 * OUT_CH + lane]);
        a3 += __ldg(&g_zl[s3 * OUT_CH + lane]);
    }
    for (; i < end; i++) a0 += __ldg(&g_zl[g_col[i] * OUT_CH + lane]);
    float r = ((a0 + a1) + (a2 + a3)) * g_invdeg[w];
    out[w * OUT_CH + lane] = r + g_r2[w * OUT_CH + lane] + __ldg(&b2[lane]);
}

// ---------------------------------------------------------------------------
extern "C" void kernel_launch(void* const* d_in, const int* in_sizes, int n_in,
                              void* d_out, int out_size) {
    const float* x   = (const float*)d_in[0];
    const void*  ei  = d_in[1];
    const float* W1l = (const float*)d_in[2];
    const float* W1r = (const float*)d_in[3];
    const float* b1  = (const float*)d_in[4];
    const float* W2l = (const float*)d_in[5];
    const float* W2r = (const float*)d_in[6];
    const float* b2  = (const float*)d_in[7];
    float* out = (float*)d_out;

    const int EB = (NE + 255) / 256;          // 6250

    k_detect<<<1, 32>>>((const int*)ei);
    k_zero_cnt<<<NB_N, 256>>>();
    k_hist<<<EB, 256>>>(ei);
    k_scanA<<<NB_N, 256>>>();
    k_scanB<<<1, 512>>>();
    k_scanC<<<NB_N, 256>>>();
    k_fill<<<EB, 256>>>(ei);
    k_gather1<<<(NN * 32 + 255) / 256, 256>>>(x);
    k_combine1<<<NB_N, 256>>>(x, W1l, W1r, b1);
    k_pre2<<<NB_N, 256>>>(W2l, W2r);
    k_out<<<(NN * 32 + 255) / 256, 256>>>(b2, out);
}

// round 14
// speedup vs baseline: 4.5004x; 1.1631x over previous
#include <cuda_runtime.h>

#define NN     100000
#define NE     1600000
#define IN_CH  32
#define HID    128
#define OUT_CH 32
#define NB_N   ((NN + 255) / 256)   // 391 node blocks

// Packed f32x2 helpers (sm_103a FFMA2 path — only reachable via PTX)
#define PK2(d, lo, hi)  asm("mov.b64 %0, {%1, %2};" : "=l"(d) : "f"(lo), "f"(hi))
#define UPK2(lo, hi, s) asm("mov.b64 {%0, %1}, %2;" : "=f"(lo), "=f"(hi) : "l"(s))
#define FMA2(d, a, b, c) \
    asm("fma.rn.f32x2 %0, %1, %2, %3;" : "=l"(d) : "l"(a), "l"(b), "l"(c))

// ---------------- Scratch (device globals; no allocation allowed) ----------
__device__ int   g_is64;
__device__ int   g_cnt[NN];
__device__ int   g_fill[NN];
__device__ int   g_rowptr[NN + 1];
__device__ int   g_col[NE];
__device__ int   g_bsum[NB_N];
__device__ int   g_boff[NB_N];
__device__ __align__(16) float g_invdeg[NN];
__device__ __align__(16) float g_agg1[NN * IN_CH];        // mean-aggregated x
__device__ __align__(16) float g_h[(size_t)NN * HID];     // layer-1 output
__device__ __align__(16) float g_zl[NN * OUT_CH];         // h @ W2l^T
__device__ __align__(16) float g_r2[NN * OUT_CH];         // h @ W2r^T

__device__ __forceinline__ int load_idx(const void* ei, long long pos, int is64) {
    if (is64) return (int)((const long long*)ei)[pos];
    return ((const int*)ei)[pos];
}

__global__ void k_detect(const int* __restrict__ ei32) {
    if (threadIdx.x == 0 && blockIdx.x == 0) {
        int odd_nonzero = 0;
        for (int i = 1; i < 1024; i += 2) odd_nonzero |= (ei32[i] != 0);
        g_is64 = odd_nonzero ? 0 : 1;
    }
}

// ---------------- CSR build ------------------------------------------------
__global__ void k_zero_cnt() {
    int i = blockIdx.x * blockDim.x + threadIdx.x;
    if (i < NN) { g_cnt[i] = 0; g_fill[i] = 0; }
}

__global__ void k_hist(const void* __restrict__ ei) {
    int e = blockIdx.x * blockDim.x + threadIdx.x;
    if (e >= NE) return;
    int dst = load_idx(ei, (long long)NE + e, g_is64);
    if ((unsigned)dst < NN) atomicAdd(&g_cnt[dst], 1);
}

__global__ __launch_bounds__(256) void k_scanA() {
    __shared__ int s[256];
    int tid = threadIdx.x;
    int idx = blockIdx.x * 256 + tid;
    s[tid] = (idx < NN) ? g_cnt[idx] : 0;
    __syncthreads();
    for (int off = 128; off > 0; off >>= 1) {
        if (tid < off) s[tid] += s[tid + off];
        __syncthreads();
    }
    if (tid == 0) g_bsum[blockIdx.x] = s[0];
}

__global__ __launch_bounds__(512) void k_scanB() {
    __shared__ int s[512];
    int tid = threadIdx.x;
    int v = (tid < NB_N) ? g_bsum[tid] : 0;
    s[tid] = v;
    __syncthreads();
    for (int off = 1; off < 512; off <<= 1) {
        int t = 0;
        if (tid >= off) t = s[tid - off];
        __syncthreads();
        if (tid >= off) s[tid] += t;
        __syncthreads();
    }
    if (tid < NB_N) g_boff[tid] = s[tid] - v;          // exclusive
    if (tid == NB_N - 1) g_rowptr[NN] = s[tid];        // total
}

__global__ __launch_bounds__(256) void k_scanC() {
    __shared__ int s[256];
    int tid = threadIdx.x;
    int idx = blockIdx.x * 256 + tid;
    int c = (idx < NN) ? g_cnt[idx] : 0;
    s[tid] = c;
    __syncthreads();
    for (int off = 1; off < 256; off <<= 1) {
        int t = 0;
        if (tid >= off) t = s[tid - off];
        __syncthreads();
        if (tid >= off) s[tid] += t;
        __syncthreads();
    }
    if (idx < NN) {
        g_rowptr[idx] = g_boff[blockIdx.x] + s[tid] - c;
        g_invdeg[idx] = 1.0f / fmaxf((float)c, 1.0f);
    }
}

__global__ void k_fill(const void* __restrict__ ei) {
    int e = blockIdx.x * blockDim.x + threadIdx.x;
    if (e >= NE) return;
    int is64 = g_is64;
    int src = load_idx(ei, e, is64);
    int dst = load_idx(ei, (long long)NE + e, is64);
    if ((unsigned)src >= NN || (unsigned)dst >= NN) return;
    int pos = g_rowptr[dst] + atomicAdd(&g_fill[dst], 1);
    g_col[pos] = src;
}

// ---------------- Layer-1 gather: agg1[n] = mean_{s in N(n)} x[s]  ---------
__global__ __launch_bounds__(256) void k_gather1(const float* __restrict__ x) {
    int w = (blockIdx.x * blockDim.x + threadIdx.x) >> 5;
    int lane = threadIdx.x & 31;
    if (w >= NN) return;
    int beg = g_rowptr[w], end = g_rowptr[w + 1];
    float acc0 = 0.f, acc1 = 0.f;
    int i = beg;
    for (; i + 1 < end; i += 2) {
        int s0 = g_col[i], s1 = g_col[i + 1];
        acc0 += __ldg(&x[s0 * IN_CH + lane]);
        acc1 += __ldg(&x[s1 * IN_CH + lane]);
    }
    if (i < end) acc0 += __ldg(&x[g_col[i] * IN_CH + lane]);
    g_agg1[w * IN_CH + lane] = (acc0 + acc1) * g_invdeg[w];
}

// ---------------- Layer-1 combine: h = relu(agg1@W1l^T + x@W1r^T + b1) -----
// 256 nodes/block; warp handles 4 nodes/pass; FFMA2 packed math.
__global__ __launch_bounds__(256) void k_combine1(
        const float* __restrict__ x,
        const float* __restrict__ W1l,
        const float* __restrict__ W1r,
        const float* __restrict__ b1) {
    __shared__ __align__(16) float sWl[IN_CH * HID];   // [c*128 + o]
    __shared__ __align__(16) float sWr[IN_CH * HID];
    __shared__ __align__(16) float sb[HID];

    int tid = threadIdx.x;
    const float4* Wl4 = (const float4*)W1l;            // elem i*4 = o*32 + c4*4
    const float4* Wr4 = (const float4*)W1r;
    for (int i = tid; i < IN_CH * HID / 4; i += 256) {
        int o = i >> 3, c4 = i & 7;
        float4 v = Wl4[i];
        sWl[(c4 * 4 + 0) * HID + o] = v.x;
        sWl[(c4 * 4 + 1) * HID + o] = v.y;
        sWl[(c4 * 4 + 2) * HID + o] = v.z;
        sWl[(c4 * 4 + 3) * HID + o] = v.w;
        v = Wr4[i];
        sWr[(c4 * 4 + 0) * HID + o] = v.x;
        sWr[(c4 * 4 + 1) * HID + o] = v.y;
        sWr[(c4 * 4 + 2) * HID + o] = v.z;
        sWr[(c4 * 4 + 3) * HID + o] = v.w;
    }
    if (tid < HID) sb[tid] = b1[tid];
    __syncthreads();

    int warp = tid >> 5, lane = tid & 31;
    int nbase = blockIdx.x * 256;
    const float4* a4 = (const float4*)g_agg1;
    const float4* x4 = (const float4*)x;
    const float4* sWl4 = (const float4*)sWl;
    const float4* sWr4 = (const float4*)sWr;
    float4 bb = ((const float4*)sb)[lane];
    float4 z = make_float4(0.f, 0.f, 0.f, 0.f);

    for (int it = warp; it < 64; it += 8) {
        int n0 = nbase + it * 4;
        if (n0 >= NN) break;
        unsigned long long a01[4] = {0ull, 0ull, 0ull, 0ull};
        unsigned long long a23[4] = {0ull, 0ull, 0ull, 0ull};
#pragma unroll
        for (int c4 = 0; c4 < 8; c4++) {
            float4 av[4], xv[4];
#pragma unroll
            for (int k = 0; k < 4; k++) {
                int n = n0 + k;
                bool ok = (n < NN);
                av[k] = ok ? a4[n * 8 + c4] : z;
                xv[k] = ok ? x4[n * 8 + c4] : z;
            }
#pragma unroll
            for (int j = 0; j < 4; j++) {
                int c = c4 * 4 + j;
                float4 wl = sWl4[c * 32 + lane];
                float4 wr = sWr4[c * 32 + lane];
                unsigned long long wl01, wl23, wr01, wr23;
                PK2(wl01, wl.x, wl.y); PK2(wl23, wl.z, wl.w);
                PK2(wr01, wr.x, wr.y); PK2(wr23, wr.z, wr.w);
#pragma unroll
                for (int k = 0; k < 4; k++) {
                    float a = ((const float*)&av[k])[j];
                    float xx = ((const float*)&xv[k])[j];
                    unsigned long long a2, x2;
                    PK2(a2, a, a);
                    PK2(x2, xx, xx);
                    FMA2(a01[k], a2, wl01, a01[k]);
                    FMA2(a01[k], x2, wr01, a01[k]);
                    FMA2(a23[k], a2, wl23, a23[k]);
                    FMA2(a23[k], x2, wr23, a23[k]);
                }
            }
        }
#pragma unroll
        for (int k = 0; k < 4; k++) {
            int n = n0 + k;
            if (n < NN) {
                float f0, f1, f2, f3;
                UPK2(f0, f1, a01[k]);
                UPK2(f2, f3, a23[k]);
                float4 o;
                o.x = fmaxf(f0 + bb.x, 0.f);
                o.y = fmaxf(f1 + bb.y, 0.f);
                o.z = fmaxf(f2 + bb.z, 0.f);
                o.w = fmaxf(f3 + bb.w, 0.f);
                ((float4*)g_h)[(size_t)n * (HID / 4) + lane] = o;
            }
        }
    }
}

// ---------------- Layer-2 dense pre-pass: zl = h@W2l^T, r2 = h@W2r^T -------
// (aggregation is linear: mean(h)@W = mean(h@W), so project BEFORE gather)
// 2 nodes/thread (n, n+4) to amortize weight packs; FFMA2 packed math.
__global__ __launch_bounds__(256) void k_pre2(
        const float* __restrict__ W2l,
        const float* __restrict__ W2r) {
    __shared__ __align__(16) float sWl[HID * OUT_CH];  // [c*32 + o]
    __shared__ __align__(16) float sWr[HID * OUT_CH];

    int tid = threadIdx.x;
    const float4* Wl4 = (const float4*)W2l;            // elem i*4 = o*128 + c4*4
    const float4* Wr4 = (const float4*)W2r;
    for (int i = tid; i < HID * OUT_CH / 4; i += 256) {
        int o = i >> 5, c4 = i & 31;
        float4 v = Wl4[i];
        sWl[(c4 * 4 + 0) * OUT_CH + o] = v.x;
        sWl[(c4 * 4 + 1) * OUT_CH + o] = v.y;
        sWl[(c4 * 4 + 2) * OUT_CH + o] = v.z;
        sWl[(c4 * 4 + 3) * OUT_CH + o] = v.w;
        v = Wr4[i];
        sWr[(c4 * 4 + 0) * OUT_CH + o] = v.x;
        sWr[(c4 * 4 + 1) * OUT_CH + o] = v.y;
        sWr[(c4 * 4 + 2) * OUT_CH + o] = v.z;
        sWr[(c4 * 4 + 3) * OUT_CH + o] = v.w;
    }
    __syncthreads();

    int warp = tid >> 5, lane = tid & 31;
    int ksub = lane >> 3;      // node sub-index 0..3
    int g = lane & 7;          // output quad 0..7
    int nbase = blockIdx.x * 256;
    const float4* h4 = (const float4*)g_h;
    const float4* sWl4 = (const float4*)sWl;
    const float4* sWr4 = (const float4*)sWr;
    float4 z = make_float4(0.f, 0.f, 0.f, 0.f);

    for (int it = warp; it < 32; it += 8) {
        int nA = nbase + it * 8 + ksub;       // node A
        int nB = nA + 4;                      // node B
        bool okA = (nA < NN), okB = (nB < NN);
        size_t ba = okA ? (size_t)nA * 32 : 0;
        size_t bbx = okB ? (size_t)nB * 32 : 0;
        unsigned long long lA01 = 0, lA23 = 0, rA01 = 0, rA23 = 0;
        unsigned long long lB01 = 0, lB23 = 0, rB01 = 0, rB23 = 0;
#pragma unroll 4
        for (int c4 = 0; c4 < 32; c4++) {
            float4 hA = okA ? h4[ba + c4] : z;
            float4 hB = okB ? h4[bbx + c4] : z;
#pragma unroll
            for (int j = 0; j < 4; j++) {
                int c = c4 * 4 + j;
                float4 wl = sWl4[c * 8 + g];
                float4 wr = sWr4[c * 8 + g];
                unsigned long long wl01, wl23, wr01, wr23;
                PK2(wl01, wl.x, wl.y); PK2(wl23, wl.z, wl.w);
                PK2(wr01, wr.x, wr.y); PK2(wr23, wr.z, wr.w);
                float a = ((const float*)&hA)[j];
                float b = ((const float*)&hB)[j];
                unsigned long long a2, b2p;
                PK2(a2, a, a);
                PK2(b2p, b, b);
                FMA2(lA01, a2, wl01, lA01);
                FMA2(lA23, a2, wl23, lA23);
                FMA2(rA01, a2, wr01, rA01);
                FMA2(rA23, a2, wr23, rA23);
                FMA2(lB01, b2p, wl01, lB01);
                FMA2(lB23, b2p, wl23, lB23);
                FMA2(rB01, b2p, wr01, rB01);
                FMA2(rB23, b2p, wr23, rB23);
            }
        }
        if (okA) {
            float4 ol, orr;
            UPK2(ol.x, ol.y, lA01); UPK2(ol.z, ol.w, lA23);
            UPK2(orr.x, orr.y, rA01); UPK2(orr.z, orr.w, rA23);
            ((float4*)g_zl)[nA * (OUT_CH / 4) + g] = ol;
            ((float4*)g_r2)[nA * (OUT_CH / 4) + g] = orr;
        }
        if (okB) {
            float4 ol, orr;
            UPK2(ol.x, ol.y, lB01); UPK2(ol.z, ol.w, lB23);
            UPK2(orr.x, orr.y, rB01); UPK2(orr.z, orr.w, rB23);
            ((float4*)g_zl)[nB * (OUT_CH / 4) + g] = ol;
            ((float4*)g_r2)[nB * (OUT_CH / 4) + g] = orr;
        }
    }
}

// ---------------- Output: out[n] = mean_{s in N(n)} zl[s] + r2[n] + b2 -----
__global__ __launch_bounds__(256) void k_out(const float* __restrict__ b2,
                                             float* __restrict__ out) {
    int w = (blockIdx.x * blockDim.x + threadIdx.x) >> 5;
    int lane = threadIdx.x & 31;
    if (w >= NN) return;
    int beg = g_rowptr[w], end = g_rowptr[w + 1];
    float a0 = 0.f, a1 = 0.f, a2 = 0.f, a3 = 0.f;
    int i = beg;
    for (; i + 3 < end; i += 4) {
        int s0 = g_col[i], s1 = g_col[i + 1], s2 = g_col[i + 2], s3 = g_col[i + 3];
        a0 += __ldg(&g_zl[s0 * OUT_CH + lane]);
        a1 += __ldg(&g_zl[s1 * OUT_CH + lane]);
        a2 += __ldg(&g_zl[s2 * OUT_CH + lane]);
        a3 += __ldg(&g_zl[s3 * OUT_CH + lane]);
    }
    for (; i < end; i++) a0 += __ldg(&g_zl[g_col[i] * OUT_CH + lane]);
    float r = ((a0 + a1) + (a2 + a3)) * g_invdeg[w];
    out[w * OUT_CH + lane] = r + g_r2[w * OUT_CH + lane] + __ldg(&b2[lane]);
}

// ---------------------------------------------------------------------------
extern "C" void kernel_launch(void* const* d_in, const int* in_sizes, int n_in,
                              void* d_out, int out_size) {
    const float* x   = (const float*)d_in[0];
    const void*  ei  = d_in[1];
    const float* W1l = (const float*)d_in[2];
    const float* W1r = (const float*)d_in[3];
    const float* b1  = (const float*)d_in[4];
    const float* W2l = (const float*)d_in[5];
    const float* W2r = (const float*)d_in[6];
    const float* b2  = (const float*)d_in[7];
    float* out = (float*)d_out;

    const int EB = (NE + 255) / 256;          // 6250

    k_detect<<<1, 32>>>((const int*)ei);
    k_zero_cnt<<<NB_N, 256>>>();
    k_hist<<<EB, 256>>>(ei);
    k_scanA<<<NB_N, 256>>>();
    k_scanB<<<1, 512>>>();
    k_scanC<<<NB_N, 256>>>();
    k_fill<<<EB, 256>>>(ei);
    k_gather1<<<(NN * 32 + 255) / 256, 256>>>(x);
    k_combine1<<<NB_N, 256>>>(x, W1l, W1r, b1);
    k_pre2<<<NB_N, 256>>>(W2l, W2r);
    k_out<<<(NN * 32 + 255) / 256, 256>>>(b2, out);
}